// round 6
// baseline (speedup 1.0000x reference)
#include <cuda_runtime.h>
#include <cstdint>

#define BB 32
#define LL 2048
#define DD 64

#define QKQ 128          // q rows per CTA (both GEMM kernels)
#define KT  64           // k per tile
#define NKT (LL / KT)    // 32
#define QSP 68           // [128 x 68] score/q operand stride
#define KSP 68           // [64 x 68] k/v operand stride

__device__ float g_qn[(size_t)BB * LL * DD];   // tf32-rounded normalized q
__device__ float g_kn[(size_t)BB * LL * DD];   // tf32-rounded normalized k
__device__ float g_rinv[(size_t)BB * LL];

// ---------------- helpers ----------------
__device__ __forceinline__ uint32_t f2tf32(float x) {
    uint32_t u;
    asm("cvt.rna.tf32.f32 %0, %1;" : "=r"(u) : "f"(x));
    return u;
}
__device__ __forceinline__ void mma_tf32(float* c, const uint32_t* a, const uint32_t* b) {
    asm volatile(
        "mma.sync.aligned.m16n8k8.row.col.f32.tf32.tf32.f32 "
        "{%0,%1,%2,%3}, {%4,%5,%6,%7}, {%8,%9}, {%0,%1,%2,%3};"
        : "+f"(c[0]), "+f"(c[1]), "+f"(c[2]), "+f"(c[3])
        : "r"(a[0]), "r"(a[1]), "r"(a[2]), "r"(a[3]), "r"(b[0]), "r"(b[1]));
}

// ---------- Kernel 1: L2-normalize q,k rows; output rounded to tf32 ----------
__global__ __launch_bounds__(256) void norm_kernel(const float* __restrict__ q,
                                                   const float* __restrict__ k) {
    int t = threadIdx.x;
    int rowInBlk = t >> 4;
    int lane = t & 15;
    long long row = (long long)blockIdx.x * 16 + rowInBlk;

    const float* src;
    float* dst;
    long long r2 = row;
    if (r2 < (long long)BB * LL) {
        src = q; dst = g_qn;
    } else {
        src = k; dst = g_kn; r2 -= (long long)BB * LL;
    }
    const float4 v = *(const float4*)(src + r2 * DD + lane * 4);
    float ss = v.x * v.x + v.y * v.y + v.z * v.z + v.w * v.w;
#pragma unroll
    for (int o = 8; o; o >>= 1) ss += __shfl_xor_sync(0xffffffffu, ss, o, 16);
    float inv = 1.0f / fmaxf(sqrtf(ss), 1e-12f);
    float4 o4;
    o4.x = __uint_as_float(f2tf32(v.x * inv));
    o4.y = __uint_as_float(f2tf32(v.y * inv));
    o4.z = __uint_as_float(f2tf32(v.z * inv));
    o4.w = __uint_as_float(f2tf32(v.w * inv));
    *(float4*)(dst + r2 * DD + lane * 4) = o4;
}

// ---------- Kernel 2: QK scores via tf32 HMMA; raw masked (+1) + rowsums ----------
// grid (LL/QKQ=16, BB), 256 threads (8 warps). Warp w: mi=w&3 (32q), ni=w>>2 (32k).
__global__ __launch_bounds__(256, 2) void qk_kernel(const int* __restrict__ mask,
                                                    float* __restrict__ attn) {
    extern __shared__ float sm[];
    float* qs = sm;                     // [128][QSP]
    float* ks = sm + 128 * QSP;         // [64][KSP]
    float* part = ks + 64 * KSP;        // [128][2]

    const int b = blockIdx.y;
    const int q0 = blockIdx.x * QKQ;
    const int t = threadIdx.x;
    const int w = t >> 5, lane = t & 31;
    const int g = lane >> 2, c = lane & 3;
    const int mi = w & 3, ni = w >> 2;
    const int m0 = mi * 32, n0 = ni * 32;

    // stage q tile (already tf32 bits)
    {
        int r = t >> 1, h = t & 1;
        const float4* src = (const float4*)(g_qn + ((size_t)b * LL + q0 + r) * DD + h * 32);
#pragma unroll
        for (int i = 0; i < 8; i++)
            *(float4*)&qs[r * QSP + h * 32 + i * 4] = src[i];
    }
    const float* kn = g_kn + (size_t)b * LL * DD;

    float rs[4] = {0.f, 0.f, 0.f, 0.f};

    const int kr = t >> 2, kq = t & 3;
    for (int kt = 0; kt < NKT; kt++) {
        // prefetch k tile 64x64
        const float4* ksrc = (const float4*)(kn + ((size_t)kt * KT + kr) * DD + kq * 16);
        float4 kv0 = ksrc[0], kv1 = ksrc[1], kv2 = ksrc[2], kv3 = ksrc[3];
        __syncthreads();
        *(float4*)&ks[kr * KSP + kq * 16 + 0]  = kv0;
        *(float4*)&ks[kr * KSP + kq * 16 + 4]  = kv1;
        *(float4*)&ks[kr * KSP + kq * 16 + 8]  = kv2;
        *(float4*)&ks[kr * KSP + kq * 16 + 12] = kv3;
        __syncthreads();

        float acc[2][4][4];
#pragma unroll
        for (int mf = 0; mf < 2; mf++)
#pragma unroll
            for (int nf = 0; nf < 4; nf++)
#pragma unroll
                for (int e = 0; e < 4; e++) acc[mf][nf][e] = 0.f;

#pragma unroll
        for (int s = 0; s < 8; s++) {
            uint32_t a[2][4];
#pragma unroll
            for (int mf = 0; mf < 2; mf++) {
                int rbase = (m0 + mf * 16 + g) * QSP + s * 8 + c;
                a[mf][0] = __float_as_uint(qs[rbase]);
                a[mf][1] = __float_as_uint(qs[rbase + 8 * QSP]);
                a[mf][2] = __float_as_uint(qs[rbase + 4]);
                a[mf][3] = __float_as_uint(qs[rbase + 8 * QSP + 4]);
            }
#pragma unroll
            for (int nf = 0; nf < 4; nf++) {
                int nbase = (n0 + nf * 8 + g) * KSP + s * 8 + c;
                uint32_t bb[2];
                bb[0] = __float_as_uint(ks[nbase]);
                bb[1] = __float_as_uint(ks[nbase + 4]);
                mma_tf32(acc[0][nf], a[0], bb);
                mma_tf32(acc[1][nf], a[1], bb);
            }
        }

        // epilogue: mask (int32), +1, raw write (streaming), rowsums
#pragma unroll
        for (int mf = 0; mf < 2; mf++) {
            int row0 = q0 + m0 + mf * 16 + g;
            const int* mr0 = mask + ((size_t)b * LL + row0) * LL;
            const int* mr1 = mr0 + (size_t)8 * LL;
            float* ar0 = attn + ((size_t)b * LL + row0) * LL;
            float* ar1 = ar0 + (size_t)8 * LL;
#pragma unroll
            for (int nf = 0; nf < 4; nf++) {
                size_t col = (size_t)kt * KT + n0 + nf * 8 + 2 * c;
                int2 mA = __ldcs((const int2*)(mr0 + col));
                int2 mB = __ldcs((const int2*)(mr1 + col));
                float s0 = mA.x ? 0.f : acc[mf][nf][0] + 1.f;
                float s1 = mA.y ? 0.f : acc[mf][nf][1] + 1.f;
                float s2 = mB.x ? 0.f : acc[mf][nf][2] + 1.f;
                float s3 = mB.y ? 0.f : acc[mf][nf][3] + 1.f;
                __stcs((float2*)(ar0 + col), make_float2(s0, s1));
                __stcs((float2*)(ar1 + col), make_float2(s2, s3));
                rs[mf * 2 + 0] += s0 + s1;
                rs[mf * 2 + 1] += s2 + s3;
            }
        }
    }

    // reduce rowsums: lanes c=0..3 hold same rows
#pragma unroll
    for (int i = 0; i < 4; i++) {
        float vsum = rs[i];
        vsum += __shfl_xor_sync(0xffffffffu, vsum, 1);
        vsum += __shfl_xor_sync(0xffffffffu, vsum, 2);
        rs[i] = vsum;
    }
    if (c == 0) {
        part[(m0 + g) * 2 + ni]      = rs[0];
        part[(m0 + g + 8) * 2 + ni]  = rs[1];
        part[(m0 + g + 16) * 2 + ni] = rs[2];
        part[(m0 + g + 24) * 2 + ni] = rs[3];
    }
    __syncthreads();
    if (t < 128)
        g_rinv[(size_t)b * LL + q0 + t] =
            1.0f / fmaxf(part[t * 2] + part[t * 2 + 1], 1e-12f);
}

// ---------- Kernel 3: rescale attn + PV GEMM (tf32 HMMA, single-pass V) ----------
// grid (16, BB), 256 threads. Warp w: mi=w&3 (32q), ni=w>>2 (32d).
__global__ __launch_bounds__(256, 2) void pv_kernel(const float* __restrict__ v,
                                                    float* __restrict__ attn,
                                                    float* __restrict__ out) {
    extern __shared__ float sm[];
    float* ss = sm;                     // [128][QSP] tf32 scores
    float* vh = sm + 128 * QSP;         // [64 d][KSP] tf32 V (transposed)
    float* rinv = vh + 64 * KSP;        // [128]

    const int b = blockIdx.y;
    const int q0 = blockIdx.x * QKQ;
    const int t = threadIdx.x;
    const int w = t >> 5, lane = t & 31;
    const int g = lane >> 2, c = lane & 3;
    const int mi = w & 3, ni = w >> 2;
    const int m0 = mi * 32, n0 = ni * 32;

    if (t < 128) rinv[t] = g_rinv[(size_t)b * LL + q0 + t];

    float acc[2][4][4];
#pragma unroll
    for (int mf = 0; mf < 2; mf++)
#pragma unroll
        for (int nf = 0; nf < 4; nf++)
#pragma unroll
            for (int e = 0; e < 4; e++) acc[mf][nf][e] = 0.f;

    const float* vb = v + (size_t)b * LL * DD;
    const int ar = t >> 1, ah = t & 1;      // attn staging: row, half
    const int vd = t & 63, vq = t >> 6;     // v staging: d, k-quarter
    float* abase = attn + ((size_t)b * LL + q0 + ar) * LL + ah * 32;

    __syncthreads();

    for (int kt = 0; kt < NKT; kt++) {
        // prefetch raw attn (8 float4 per thread, streaming read)
        float4 araw[8];
        float* ap = abase + (size_t)kt * KT;
#pragma unroll
        for (int i = 0; i < 8; i++) araw[i] = __ldcs((const float4*)(ap + i * 4));

        __syncthreads();   // previous GEMM done reading smem

        // scale, write final attn (streaming), store tf32 scores
        float ri = rinv[ar];
#pragma unroll
        for (int i = 0; i < 8; i++) {
            float4 x = araw[i];
            x.x *= ri; x.y *= ri; x.z *= ri; x.w *= ri;
            __stcs((float4*)(ap + i * 4), x);
            float4 tx;
            tx.x = __uint_as_float(f2tf32(x.x));
            tx.y = __uint_as_float(f2tf32(x.y));
            tx.z = __uint_as_float(f2tf32(x.z));
            tx.w = __uint_as_float(f2tf32(x.w));
            *(float4*)&ss[ar * QSP + ah * 32 + i * 4] = tx;
        }
        // stage v transposed (tf32): vh[d][k]
#pragma unroll
        for (int j = 0; j < 16; j++) {
            int kk = vq * 16 + j;
            float x = vb[((size_t)kt * KT + kk) * DD + vd];
            vh[vd * KSP + kk] = __uint_as_float(f2tf32(x));
        }
        __syncthreads();

        // GEMM: out += S * Vh
#pragma unroll
        for (int s = 0; s < 8; s++) {
            uint32_t a[2][4];
#pragma unroll
            for (int mf = 0; mf < 2; mf++) {
                int rbase = (m0 + mf * 16 + g) * QSP + s * 8 + c;
                a[mf][0] = __float_as_uint(ss[rbase]);
                a[mf][1] = __float_as_uint(ss[rbase + 8 * QSP]);
                a[mf][2] = __float_as_uint(ss[rbase + 4]);
                a[mf][3] = __float_as_uint(ss[rbase + 8 * QSP + 4]);
            }
#pragma unroll
            for (int nf = 0; nf < 4; nf++) {
                int nbase = (n0 + nf * 8 + g) * KSP + s * 8 + c;
                uint32_t bh[2];
                bh[0] = __float_as_uint(vh[nbase]);
                bh[1] = __float_as_uint(vh[nbase + 4]);
                mma_tf32(acc[0][nf], a[0], bh);
                mma_tf32(acc[1][nf], a[1], bh);
            }
        }
    }

    // epilogue: write out tile
#pragma unroll
    for (int mf = 0; mf < 2; mf++) {
        int row0 = q0 + m0 + mf * 16 + g;
        float* o0 = out + (size_t)((size_t)b * LL + row0) * DD;
        float* o1 = o0 + (size_t)8 * DD;
#pragma unroll
        for (int nf = 0; nf < 4; nf++) {
            int col = n0 + nf * 8 + 2 * c;
            *(float2*)(o0 + col) = make_float2(acc[mf][nf][0], acc[mf][nf][1]);
            *(float2*)(o1 + col) = make_float2(acc[mf][nf][2], acc[mf][nf][3]);
        }
    }
}

// ---------------- launch ----------------
extern "C" void kernel_launch(void* const* d_in, const int* in_sizes, int n_in,
                              void* d_out, int out_size) {
    const float* q = (const float*)d_in[0];
    const float* k = (const float*)d_in[1];
    const float* v = (const float*)d_in[2];
    const int* mask = (const int*)d_in[3];

    float* out = (float*)d_out;
    float* attn = out + (size_t)BB * LL * DD;

    const int QK_SMEM = (128 * QSP + 64 * KSP + 256) * (int)sizeof(float);
    const int PV_SMEM = (128 * QSP + 64 * KSP + 128) * (int)sizeof(float);

    cudaFuncSetAttribute(qk_kernel, cudaFuncAttributeMaxDynamicSharedMemorySize, QK_SMEM);
    cudaFuncSetAttribute(pv_kernel, cudaFuncAttributeMaxDynamicSharedMemorySize, PV_SMEM);

    norm_kernel<<<(2 * BB * LL) / 16, 256>>>(q, k);
    qk_kernel<<<dim3(LL / QKQ, BB), 256, QK_SMEM>>>(mask, attn);
    pv_kernel<<<dim3(LL / QKQ, BB), 256, PV_SMEM>>>(v, attn, out);
}